// round 17
// baseline (speedup 1.0000x reference)
#include <cuda_runtime.h>
#include <cuda_bf16.h>
#include <math.h>
#include <stdint.h>

#define BATCH 8
#define NV 2048
#define NP 4096
#define DIM 64

// query rows: 3 segs (h,m,l) x 64 bf16 = 384B.  key rows: 6 segs (h,m,l,h,m,h) = 768B
#define PITCH_A 400
#define PITCH_B 784
#define SZ_A (128 * PITCH_A)   // 51200
#define SZ_B (32 * PITCH_B)    // 25088
#define OFF_A 0
#define OFF_B0 SZ_A
#define OFF_B1 (SZ_A + SZ_B)
#define DYN_SMEM (SZ_A + 2 * SZ_B)  // 101376 -> 2 blocks/SM

// ---------------- scratch (device globals; no allocation) ----------------
__device__ uint4 g_q3[BATCH * NV * 24];   // query rows: [ah|am|al]      (384B)
__device__ uint4 g_k1[BATCH * NP * 48];   // unit pf keys: [h|m|l|h|m|h] (768B)
__device__ uint4 g_k2[BATCH * NV * 48];   // unit vf keys: [h|m|l|h|m|h]
__device__ float g_vm[BATCH * NV];
__device__ float g_flow[BATCH * NV * 3];
__device__ int   g_invis_list[BATCH * NV];
__device__ int   g_vis_list[BATCH * NV];
__device__ int   g_invis_cnt[BATCH];
__device__ int   g_vis_cnt[BATCH];
__device__ int   g_s2idx[BATCH * NV * 8];

// ---------------- f32x2 helpers (exact fp32 epilogues) ----------------
__device__ __forceinline__ void fma2(unsigned long long& d, unsigned long long a,
                                     unsigned long long b) {
    asm("fma.rn.f32x2 %0, %1, %2, %0;" : "+l"(d) : "l"(a), "l"(b));
}
__device__ __forceinline__ unsigned long long add2(unsigned long long a, unsigned long long b) {
    unsigned long long d;
    asm("add.rn.f32x2 %0, %1, %2;" : "=l"(d) : "l"(a), "l"(b));
    return d;
}
__device__ __forceinline__ float f2sum(unsigned long long a) {
    return __uint_as_float((unsigned)a) + __uint_as_float((unsigned)(a >> 32));
}

// ---------------- cp.async ----------------
__device__ __forceinline__ void cp16(void* smem_dst, const void* gsrc) {
    unsigned s = (unsigned)__cvta_generic_to_shared(smem_dst);
    asm volatile("cp.async.cg.shared.global [%0], [%1], 16;" ::"r"(s), "l"(gsrc) : "memory");
}
__device__ __forceinline__ void cp_commit() {
    asm volatile("cp.async.commit_group;" ::: "memory");
}
__device__ __forceinline__ void cp_wait1() {
    asm volatile("cp.async.wait_group 1;" ::: "memory");
}
__device__ __forceinline__ void cp_wait0() {
    asm volatile("cp.async.wait_group 0;" ::: "memory");
}

// ---------------- warp-MMA primitives (baseline PTX, no sm_103a features) ----------------
__device__ __forceinline__ void ldm_x4(uint32_t (&a)[4], uint32_t addr) {
    asm volatile("ldmatrix.sync.aligned.m8n8.x4.shared.b16 {%0,%1,%2,%3}, [%4];"
                 : "=r"(a[0]), "=r"(a[1]), "=r"(a[2]), "=r"(a[3])
                 : "r"(addr));
}
__device__ __forceinline__ void ldm_x2(uint32_t (&b)[2], uint32_t addr) {
    asm volatile("ldmatrix.sync.aligned.m8n8.x2.shared.b16 {%0,%1}, [%2];"
                 : "=r"(b[0]), "=r"(b[1])
                 : "r"(addr));
}
__device__ __forceinline__ void mma16816(float (&c)[4], const uint32_t (&a)[4],
                                         const uint32_t (&b)[2]) {
    asm volatile(
        "mma.sync.aligned.m16n8k16.row.col.f32.bf16.bf16.f32 "
        "{%0,%1,%2,%3}, {%4,%5,%6,%7}, {%8,%9}, {%0,%1,%2,%3};"
        : "+f"(c[0]), "+f"(c[1]), "+f"(c[2]), "+f"(c[3])
        : "r"(a[0]), "r"(a[1]), "r"(a[2]), "r"(a[3]), "r"(b[0]), "r"(b[1]));
}
__device__ __forceinline__ uint32_t smem_u32(const void* p) {
    return (uint32_t)__cvta_generic_to_shared(p);
}

// ---------------- top-8 ----------------
__device__ __forceinline__ void topk_insert(float (&v)[8], int (&id)[8], float s, int sid,
                                            bool c) {
    v[0] = c ? s : v[0];
    id[0] = c ? sid : id[0];
#pragma unroll
    for (int j = 0; j < 7; j++) {
        const bool g = v[j] > v[j + 1];
        const float lo = fminf(v[j], v[j + 1]);
        const float hi = fmaxf(v[j], v[j + 1]);
        const int tlo = g ? id[j + 1] : id[j];
        const int thi = g ? id[j] : id[j + 1];
        v[j] = lo;
        v[j + 1] = hi;
        id[j] = tlo;
        id[j + 1] = thi;
    }
}
__device__ __forceinline__ void topk_push4(float (&v)[8], int (&id)[8], float s0, float s1,
                                           float s2, float s3, int i0, int i1, int i2,
                                           int i3) {
    float smax = s0;
    int jmax = 0, imax = i0;
    bool g;
    g = s1 > smax; smax = g ? s1 : smax; jmax = g ? 1 : jmax; imax = g ? i1 : imax;
    g = s2 > smax; smax = g ? s2 : smax; jmax = g ? 2 : jmax; imax = g ? i2 : imax;
    g = s3 > smax; smax = g ? s3 : smax; jmax = g ? 3 : jmax; imax = g ? i3 : imax;
    topk_insert(v, id, smax, imax, smax > v[0]);
    const bool r0 = (jmax != 0) & (s0 > v[0]);
    const bool r1 = (jmax != 1) & (s1 > v[0]);
    const bool r2 = (jmax != 2) & (s2 > v[0]);
    const bool r3 = (jmax != 3) & (s3 > v[0]);
    if (__ballot_sync(0xffffffffu, r0 | r1 | r2 | r3)) {
        topk_insert(v, id, s0, i0, (jmax != 0) & (s0 > v[0]));
        topk_insert(v, id, s1, i1, (jmax != 1) & (s1 > v[0]));
        topk_insert(v, id, s2, i2, (jmax != 2) & (s2 > v[0]));
        topk_insert(v, id, s3, i3, (jmax != 3) & (s3 > v[0]));
    }
}

// ---------------- tile loaders ----------------
// A: 128 query rows x 384B  (256 thr: 2/row, 12 chunks each)
__device__ __forceinline__ void load_A(char* smem, const uint4* rowsBase, const int* list,
                                       int base, int maxIdx, int tid) {
    const int r = tid >> 1;
    const int half = tid & 1;
    int row = base + r;
    if (list) row = list[min(row, maxIdx)];
    const uint4* src = rowsBase + (size_t)row * 24 + half * 12;
    char* dst = smem + OFF_A + r * PITCH_A + half * 192;
#pragma unroll
    for (int i = 0; i < 12; i++) cp16(dst + i * 16, src + i);
}
// B: 32 key rows x 768B  (256 thr: 8/row, 6 chunks each)
__device__ __forceinline__ void load_B(char* smem, int off, const uint4* rowsBase,
                                       const int* list, int base, int maxIdx, int tid) {
    const int r = tid >> 3;
    const int part = tid & 7;
    int row = base + r;
    if (list) row = list[min(row, maxIdx)];
    const uint4* src = rowsBase + (size_t)row * 48 + part * 6;
    char* dst = smem + off + r * PITCH_B + part * 96;
#pragma unroll
    for (int i = 0; i < 6; i++) cp16(dst + i * 16, src + i);
}

// map k-step (0..23 over 6 B segs) -> unique A k-step (A segs h,h,h,m,m,l)
__device__ __constant__ int c_amap[24] = {0, 1, 2, 3, 0, 1, 2, 3, 0, 1, 2, 3,
                                          4, 5, 6, 7, 4, 5, 6, 7, 8, 9, 10, 11};

// one 32-key tile: 4 nblocks interleaved, 24 k-steps; then top-8 pushes
__device__ __forceinline__ void tile_topk(uint32_t bbase, const uint32_t (&afrag)[12][4],
                                          int tilebase, int limit, int lane,
                                          float (&vA)[8], int (&idA)[8], float (&vB)[8],
                                          int (&idB)[8]) {
    float c[4][4];
#pragma unroll
    for (int j = 0; j < 4; j++) c[j][0] = c[j][1] = c[j][2] = c[j][3] = 0.f;
    const uint32_t b_row = bbase + (lane & 7) * PITCH_B + ((lane >> 3) & 1) * 16;
#pragma unroll
    for (int kk = 0; kk < 24; kk++) {
        uint32_t bf[4][2];
#pragma unroll
        for (int j = 0; j < 4; j++) ldm_x2(bf[j], b_row + j * (8 * PITCH_B) + kk * 32);
        const int au = c_amap[kk];
#pragma unroll
        for (int j = 0; j < 4; j++) mma16816(c[j], afrag[au], bf[j]);
    }
    const int cb = tilebase + 2 * (lane & 3);
#pragma unroll
    for (int p = 0; p < 2; p++) {
        const int c0 = cb + 16 * p, c1 = cb + 16 * p + 8;
        const float a0 = (c0 < limit) ? c[2 * p][0] : -1e30f;
        const float a1 = (c0 + 1 < limit) ? c[2 * p][1] : -1e30f;
        const float a2 = (c1 < limit) ? c[2 * p + 1][0] : -1e30f;
        const float a3 = (c1 + 1 < limit) ? c[2 * p + 1][1] : -1e30f;
        topk_push4(vA, idA, a0, a1, a2, a3, c0, c0 + 1, c1, c1 + 1);
        const float b0 = (c0 < limit) ? c[2 * p][2] : -1e30f;
        const float b1 = (c0 + 1 < limit) ? c[2 * p][3] : -1e30f;
        const float b2 = (c1 < limit) ? c[2 * p + 1][2] : -1e30f;
        const float b3 = (c1 + 1 < limit) ? c[2 * p + 1][3] : -1e30f;
        topk_push4(vB, idB, b0, b1, b2, b3, c0, c0 + 1, c1, c1 + 1);
    }
}

// ---------------- kernel A: vm + visibility compaction ----------------
__global__ void vm_kernel(const float* __restrict__ logits) {
    const int b = blockIdx.x;
    __shared__ float sv[NV];
    __shared__ float smin[256];
    __shared__ float smax_s[256];
    __shared__ int c_inv, c_vis;
    float lmin = 1e30f, lmax = -1e30f;
    for (int i = threadIdx.x; i < NV; i += 256) {
        float s = 1.0f / (1.0f + expf(-logits[b * NV + i]));
        sv[i] = s;
        lmin = fminf(lmin, s);
        lmax = fmaxf(lmax, s);
    }
    smin[threadIdx.x] = lmin;
    smax_s[threadIdx.x] = lmax;
    if (threadIdx.x == 0) { c_inv = 0; c_vis = 0; }
    __syncthreads();
    for (int off = 128; off > 0; off >>= 1) {
        if (threadIdx.x < off) {
            smin[threadIdx.x] = fminf(smin[threadIdx.x], smin[threadIdx.x + off]);
            smax_s[threadIdx.x] = fmaxf(smax_s[threadIdx.x], smax_s[threadIdx.x + off]);
        }
        __syncthreads();
    }
    const float mn = smin[0];
    const float inv = 1.0f / (smax_s[0] - mn);
    for (int i = threadIdx.x; i < NV; i += 256) {
        float v = (sv[i] - mn) * inv;
        g_vm[b * NV + i] = v;
        if (v >= 0.5f) {
            int p = atomicAdd(&c_vis, 1);
            g_vis_list[b * NV + p] = i;
        } else {
            int p = atomicAdd(&c_inv, 1);
            g_invis_list[b * NV + p] = i;
        }
    }
    __syncthreads();
    if (threadIdx.x == 0) {
        g_vis_cnt[b] = c_vis;
        g_invis_cnt[b] = c_inv;
    }
}

// ---------------- kernel B: 3-way split (queries 3-seg, keys 6-seg) ----------------
__device__ __forceinline__ void split3f(float x, float& h, float& m, float& l) {
    h = __bfloat162float(__float2bfloat16_rn(x));
    float r = x - h;
    m = __bfloat162float(__float2bfloat16_rn(r));
    l = r - m;
}
__device__ __forceinline__ uint32_t pack_bf2(float a, float b) {
    __nv_bfloat162 t;
    t.x = __float2bfloat16_rn(a);
    t.y = __float2bfloat16_rn(b);
    return *(uint32_t*)&t;
}
__global__ void split_kernel(const float* __restrict__ vf, const float* __restrict__ pf) {
    const int gw = (blockIdx.x * blockDim.x + threadIdx.x) >> 5;
    const int lane = threadIdx.x & 31;
    const int totalRows = BATCH * NV + BATCH * NP;
    if (gw >= totalRows) return;
    const bool isV = gw < BATCH * NV;
    const int r = isV ? gw : gw - BATCH * NV;
    const float* src = (isV ? vf : pf) + (size_t)r * DIM;
    const float2 v = ((const float2*)src)[lane];
    float ss = v.x * v.x + v.y * v.y;
#pragma unroll
    for (int o = 16; o > 0; o >>= 1) ss += __shfl_xor_sync(0xffffffffu, ss, o);
    const float inv = 1.0f / fmaxf(sqrtf(ss), 1e-12f);
    // unit-normalized split (keys)
    float uh0, um0, ul0, uh1, um1, ul1;
    split3f(v.x * inv, uh0, um0, ul0);
    split3f(v.y * inv, uh1, um1, ul1);
    uint32_t* krow = (uint32_t*)((isV ? g_k2 : g_k1) + (size_t)r * 48);
    const uint32_t ph = pack_bf2(uh0, uh1);
    const uint32_t pm = pack_bf2(um0, um1);
    const uint32_t pl = pack_bf2(ul0, ul1);
    krow[0 * 32 + lane] = ph;   // h
    krow[1 * 32 + lane] = pm;   // m
    krow[2 * 32 + lane] = pl;   // l
    krow[3 * 32 + lane] = ph;   // h
    krow[4 * 32 + lane] = pm;   // m
    krow[5 * 32 + lane] = ph;   // h
    if (isV) {
        // raw query split (ranking invariant to query scale)
        float qh0, qm0, ql0, qh1, qm1, ql1;
        split3f(v.x, qh0, qm0, ql0);
        split3f(v.y, qh1, qm1, ql1);
        uint32_t* qrow = (uint32_t*)(g_q3 + (size_t)r * 24);
        qrow[0 * 32 + lane] = pack_bf2(qh0, qh1);
        qrow[1 * 32 + lane] = pack_bf2(qm0, qm1);
        qrow[2 * 32 + lane] = pack_bf2(ql0, ql1);
    }
}

// ---------------- shared KNN body ----------------
// block: 256 thr = 8 warps, 128 queries (warp w owns rows w*16..w*16+15).
// afrag: 12 unique k-steps (3 A segs x 4).  Returns merged top-8 for query tid<128.
struct KnnOut {
    float v[8];
    int id[8];
};
__device__ __forceinline__ void knn_scan(char* smem, const uint4* keyBase, const int* klist,
                                         int nkeys, int tid, int w, int lane,
                                         float (&vA)[8], int (&idA)[8], float (&vB)[8],
                                         int (&idB)[8]) {
    // A fragments from shared (loaded by caller)
    uint32_t afrag[12][4];
    {
        const uint32_t a_base = smem_u32(smem + OFF_A) + (w * 16 + (lane & 15)) * PITCH_A +
                                ((lane >> 4) & 1) * 16;
#pragma unroll
        for (int ku = 0; ku < 12; ku++) ldm_x4(afrag[ku], a_base + ku * 32);
    }
    const int ntk = (nkeys + 31) >> 5;
    load_B(smem, OFF_B0, keyBase, klist, 0, nkeys - 1, tid);
    cp_commit();
    for (int tt = 0; tt < ntk; tt++) {
        const int buf = tt & 1;
        if (tt + 1 < ntk) {
            load_B(smem, buf ? OFF_B0 : OFF_B1, keyBase, klist, (tt + 1) * 32, nkeys - 1,
                   tid);
            cp_commit();
            cp_wait1();
        } else {
            cp_wait0();
        }
        __syncthreads();
        tile_topk(smem_u32(smem + (buf ? OFF_B1 : OFF_B0)), afrag, tt * 32, nkeys, lane, vA,
                  idA, vB, idB);
        __syncthreads();
    }
}
// publish + merge: after this, thread tid<128 holds top-8 of query tid in out
__device__ __forceinline__ void knn_merge(char* smem, int tid, int w, int lane,
                                          const float (&vA)[8], const int (&idA)[8],
                                          const float (&vB)[8], const int (&idB)[8],
                                          KnnOut& out) {
    float* mv = (float*)(smem + OFF_B0);          // [32 cand][128 q]
    int* mi = (int*)(smem + OFF_B0 + 16384);
    const int quad = lane & 3;
    const int rA = w * 16 + (lane >> 2);
    const int rB = rA + 8;
#pragma unroll
    for (int j = 0; j < 8; j++) {
        mv[(quad * 8 + j) * 128 + rA] = vA[j];
        mi[(quad * 8 + j) * 128 + rA] = idA[j];
        mv[(quad * 8 + j) * 128 + rB] = vB[j];
        mi[(quad * 8 + j) * 128 + rB] = idB[j];
    }
    __syncthreads();
    if (tid < 128) {
#pragma unroll
        for (int j = 0; j < 8; j++) { out.v[j] = -1e30f; out.id[j] = 0; }
        for (int c = 0; c < 32; c++) {
            const float s = mv[c * 128 + tid];
            topk_insert(out.v, out.id, s, mi[c * 128 + tid], s > out.v[0]);
        }
    }
}

// ---------------- stage 1 ----------------
__global__ __launch_bounds__(256, 2) void s1_mma_kernel(
    const float* __restrict__ vtx, const float* __restrict__ pts,
    const float* __restrict__ vf_raw, const float* __restrict__ pf_raw,
    float* __restrict__ out) {
    extern __shared__ char smem[];
    const int tid = threadIdx.x;
    const int w = tid >> 5;
    const int lane = tid & 31;
    const int b = blockIdx.x >> 4;
    const int q0 = (blockIdx.x & 15) * 128;

    load_A(smem, g_q3, nullptr, b * NV + q0, 0, tid);
    cp_commit();
    cp_wait0();
    __syncthreads();

    float vA[8], vB[8];
    int idA[8], idB[8];
#pragma unroll
    for (int j = 0; j < 8; j++) {
        vA[j] = -1e30f; vB[j] = -1e30f; idA[j] = 0; idB[j] = 0;
    }
    knn_scan(smem, g_k1 + (size_t)b * NP * 48, nullptr, NP, tid, w, lane, vA, idA, vB, idB);
    KnnOut o;
    knn_merge(smem, tid, w, lane, vA, idA, vB, idB, o);

    if (tid < 128) {
        const int qg = b * NV + q0 + tid;
        unsigned long long q2[32];
        const ulonglong2* qr = (const ulonglong2*)(vf_raw + (size_t)qg * DIM);
#pragma unroll
        for (int i = 0; i < 16; i++) {
            const ulonglong2 t2 = qr[i];
            q2[2 * i] = t2.x;
            q2[2 * i + 1] = t2.y;
        }
        const float vx = vtx[qg * 3 + 0];
        const float vy = vtx[qg * 3 + 1];
        const float vz = vtx[qg * 3 + 2];
        float n0 = 0.f, n1 = 0.f, n2 = 0.f, den = 0.f;
#pragma unroll
        for (int j = 0; j < 8; j++) {
            const int gp = b * NP + o.id[j];
            const ulonglong2* pr = (const ulonglong2*)(pf_raw + (size_t)gp * DIM);
            unsigned long long a0 = 0ull, a1 = 0ull;
#pragma unroll
            for (int i = 0; i < 16; i++) {
                const ulonglong2 pv = pr[i];
                fma2(a0, q2[2 * i], pv.x);
                fma2(a1, q2[2 * i + 1], pv.y);
            }
            const float f = f2sum(add2(a0, a1));
            n0 += (pts[gp * 3 + 0] - vx) * f;
            n1 += (pts[gp * 3 + 1] - vy) * f;
            n2 += (pts[gp * 3 + 2] - vz) * f;
            den += f;
        }
        const float invd = 1.0f / den;
        const float f0 = n0 * invd, f1 = n1 * invd, f2v = n2 * invd;
        g_flow[qg * 3 + 0] = f0;
        g_flow[qg * 3 + 1] = f1;
        g_flow[qg * 3 + 2] = f2v;
        out[qg * 4 + 0] = f0;
        out[qg * 4 + 1] = f1;
        out[qg * 4 + 2] = f2v;
        out[qg * 4 + 3] = g_vm[qg];
    }
}

// ---------------- stage 2 ----------------
__global__ __launch_bounds__(256, 2) void s2_mma_kernel() {
    extern __shared__ char smem[];
    const int b = blockIdx.x >> 4;
    const int q0 = (blockIdx.x & 15) * 128;
    const int cnt = g_invis_cnt[b];
    if (q0 >= cnt) return;
    const int vcnt = g_vis_cnt[b];
    const int tid = threadIdx.x;
    const int w = tid >> 5;
    const int lane = tid & 31;
    const int* ilist = g_invis_list + b * NV;
    const int* vlist = g_vis_list + b * NV;

    load_A(smem, g_q3 + (size_t)b * NV * 24, ilist, q0, cnt - 1, tid);
    cp_commit();
    cp_wait0();
    __syncthreads();

    float vA[8], vB[8];
    int idA[8], idB[8];
#pragma unroll
    for (int j = 0; j < 8; j++) {
        vA[j] = -1e30f; vB[j] = -1e30f; idA[j] = 0; idB[j] = 0;
    }
    knn_scan(smem, g_k2 + (size_t)b * NV * 48, vlist, vcnt, tid, w, lane, vA, idA, vB, idB);
    KnnOut o;
    knn_merge(smem, tid, w, lane, vA, idA, vB, idB, o);

    if (tid < 128 && q0 + tid < cnt) {
        const int qg = b * NV + ilist[q0 + tid];
#pragma unroll
        for (int j = 0; j < 8; j++) g_s2idx[qg * 8 + j] = vlist[o.id[j]];
    }
}

// ---------------- epilogue: invisible flow from stage2 neighbors ----------------
__global__ __launch_bounds__(256) void epilogue_kernel(
    const float* __restrict__ vf_raw, float* __restrict__ out) {
    const int b = blockIdx.y;
    const int cnt = g_invis_cnt[b];
    const int w = threadIdx.x >> 5;
    const int lane = threadIdx.x & 31;
    const int qslot = blockIdx.x * 8 + w;
    if (qslot >= cnt) return;
    const int qi = g_invis_list[b * NV + qslot];
    const int qg = b * NV + qi;

    float n0 = 0.f, n1 = 0.f, n2 = 0.f, den = 0.f;
    if (lane < 8) {
        const int gv = b * NV + g_s2idx[qg * 8 + lane];
        const float4* qr = (const float4*)(vf_raw + (size_t)qg * DIM);
        const float4* kr = (const float4*)(vf_raw + (size_t)gv * DIM);
        float f0 = 0.f, f1 = 0.f, f2 = 0.f, f3 = 0.f;
#pragma unroll
        for (int i = 0; i < 16; i++) {
            const float4 qv = qr[i];
            const float4 kv = kr[i];
            f0 += qv.x * kv.x;
            f1 += qv.y * kv.y;
            f2 += qv.z * kv.z;
            f3 += qv.w * kv.w;
        }
        const float f = (f0 + f1) + (f2 + f3);
        n0 = g_flow[gv * 3 + 0] * f;
        n1 = g_flow[gv * 3 + 1] * f;
        n2 = g_flow[gv * 3 + 2] * f;
        den = f;
    }
#pragma unroll
    for (int o = 4; o > 0; o >>= 1) {
        n0 += __shfl_down_sync(0xffffffffu, n0, o);
        n1 += __shfl_down_sync(0xffffffffu, n1, o);
        n2 += __shfl_down_sync(0xffffffffu, n2, o);
        den += __shfl_down_sync(0xffffffffu, den, o);
    }
    if (lane == 0) {
        const float invd = 1.0f / den;
        out[qg * 4 + 0] = n0 * invd;
        out[qg * 4 + 1] = n1 * invd;
        out[qg * 4 + 2] = n2 * invd;
        out[qg * 4 + 3] = g_vm[qg];
    }
}

// ---------------- launch ----------------
extern "C" void kernel_launch(void* const* d_in, const int* in_sizes, int n_in,
                              void* d_out, int out_size) {
    const float* vtx = (const float*)d_in[0];
    const float* pts = (const float*)d_in[1];
    const float* vf = (const float*)d_in[2];
    const float* pf = (const float*)d_in[3];
    const float* vml = (const float*)d_in[4];
    float* out = (float*)d_out;

    cudaFuncSetAttribute(s1_mma_kernel, cudaFuncAttributeMaxDynamicSharedMemorySize,
                         DYN_SMEM);
    cudaFuncSetAttribute(s2_mma_kernel, cudaFuncAttributeMaxDynamicSharedMemorySize,
                         DYN_SMEM);

    vm_kernel<<<BATCH, 256>>>(vml);
    const int rows = BATCH * (NV + NP);
    split_kernel<<<(rows * 32) / 256, 256>>>(vf, pf);
    s1_mma_kernel<<<BATCH * 16, 256, DYN_SMEM>>>(vtx, pts, vf, pf, out);
    s2_mma_kernel<<<BATCH * 16, 256, DYN_SMEM>>>();
    epilogue_kernel<<<dim3(256, BATCH), 256>>>(vf, out);
}